// round 14
// baseline (speedup 1.0000x reference)
#include <cuda_runtime.h>
#include <cuda_bf16.h>
#include <math.h>

// SpatialWeight — R10 config + L2 software prefetch in weight mainloop.
// Problem: b=2, f=8, c=64, h=w=256  (fp32)
//   k_sum[bf,c] = sum_{hw} nbr[bf,c,hw]
//   out[bf,hw]  = sigmoid( sum_c ref[bf,c,hw] * k_sum[bf,c] )
// HBM streaming: 2 x 268MB reads + 4MB write.

#define BF     16          // b*f
#define C      64
#define HW     65536       // 256*256
#define HW8    8192        // HW / 8
#define PD     4           // prefetch distance (channels ahead)

// 256-bit streaming load: 8 floats, 32B-aligned (Blackwell LDG.E.256).
__device__ __forceinline__ void ldcs_v8(const float* __restrict__ p,
                                        float& a, float& b, float& c, float& d,
                                        float& e, float& f, float& g, float& h) {
    asm volatile("ld.global.cs.v8.f32 {%0,%1,%2,%3,%4,%5,%6,%7}, [%8];"
                 : "=f"(a), "=f"(b), "=f"(c), "=f"(d),
                   "=f"(e), "=f"(f), "=f"(g), "=f"(h)
                 : "l"(p));
}

__device__ __forceinline__ void prefetch_l2(const float* p) {
    asm volatile("prefetch.global.L2 [%0];" :: "l"(p));
}

__device__ float g_ksum[BF * C];

// ---------------------------------------------------------------------------
// Kernel 1: per-channel-plane reduction. One block per (bf,c) plane (256 KB
// contiguous). 256 threads * 32 v8 streaming loads each. ~6.7-6.9 TB/s.
// ---------------------------------------------------------------------------
__global__ __launch_bounds__(256) void ksum_kernel(const float* __restrict__ nbr) {
    const int ch = blockIdx.x;                       // 0..1023 == bf*64 + c
    const float* __restrict__ p = nbr + (size_t)ch * HW;

    float s = 0.0f;
    #pragma unroll 4
    for (int i = threadIdx.x; i < HW8; i += 256) {
        float a, b, c, d, e, f, g, h;
        ldcs_v8(p + (size_t)i * 8, a, b, c, d, e, f, g, h);
        s += ((a + b) + (c + d)) + ((e + f) + (g + h));
    }

    #pragma unroll
    for (int off = 16; off > 0; off >>= 1)
        s += __shfl_xor_sync(0xffffffffu, s, off);

    __shared__ float warp_sums[8];
    const int lane = threadIdx.x & 31;
    const int wid  = threadIdx.x >> 5;
    if (lane == 0) warp_sums[wid] = s;
    __syncthreads();

    if (wid == 0) {
        float t = (lane < 8) ? warp_sums[lane] : 0.0f;
        #pragma unroll
        for (int off = 4; off > 0; off >>= 1)
            t += __shfl_xor_sync(0xffffffffu, t, off);
        if (lane == 0) g_ksum[ch] = t;
    }
}

// ---------------------------------------------------------------------------
// Kernel 2: weighted channel contraction + sigmoid (R10 shape, measured best:
// 512 blocks x 256 threads, one v8 per thread per channel, 8 KB windows).
// NEW: L2 prefetch of channel c+4's burst — one prefetch per 128B line
// (lanes where tid%4==0) — to deepen the DRAM scheduler's request queue.
// ---------------------------------------------------------------------------
__global__ __launch_bounds__(256) void weight_kernel(const float* __restrict__ ref,
                                                     float* __restrict__ out) {
    const int bf  = blockIdx.x >> 5;                     // 32 blocks per bf
    const int win = (blockIdx.x & 31) << 11;             // window base (floats)
    const int p   = win + threadIdx.x * 8;               // float index in plane
    const bool pf = (threadIdx.x & 3) == 0;              // 1 prefetch / 128B line

    __shared__ float sk[C];
    if (threadIdx.x < C) sk[threadIdx.x] = g_ksum[bf * C + threadIdx.x];
    __syncthreads();

    const float* __restrict__ base = ref + (size_t)bf * C * HW + p;

    // Prime the prefetch pipeline for channels 0..PD-1 are demand-loaded soon;
    // prefetch channels PD.. ahead inside the loop.
    float a0 = 0.f, a1 = 0.f, a2 = 0.f, a3 = 0.f;
    float a4 = 0.f, a5 = 0.f, a6 = 0.f, a7 = 0.f;

    #pragma unroll
    for (int c = 0; c < C; c++) {
        if (pf && c + PD < C)
            prefetch_l2(base + (size_t)(c + PD) * HW);

        float v0, v1, v2, v3, v4, v5, v6, v7;
        ldcs_v8(base + (size_t)c * HW, v0, v1, v2, v3, v4, v5, v6, v7);
        const float k = sk[c];
        a0 = fmaf(v0, k, a0);
        a1 = fmaf(v1, k, a1);
        a2 = fmaf(v2, k, a2);
        a3 = fmaf(v3, k, a3);
        a4 = fmaf(v4, k, a4);
        a5 = fmaf(v5, k, a5);
        a6 = fmaf(v6, k, a6);
        a7 = fmaf(v7, k, a7);
    }

    float4 r0, r1;
    r0.x = __fdividef(1.0f, 1.0f + __expf(-a0));
    r0.y = __fdividef(1.0f, 1.0f + __expf(-a1));
    r0.z = __fdividef(1.0f, 1.0f + __expf(-a2));
    r0.w = __fdividef(1.0f, 1.0f + __expf(-a3));
    r1.x = __fdividef(1.0f, 1.0f + __expf(-a4));
    r1.y = __fdividef(1.0f, 1.0f + __expf(-a5));
    r1.z = __fdividef(1.0f, 1.0f + __expf(-a6));
    r1.w = __fdividef(1.0f, 1.0f + __expf(-a7));

    float4* o = reinterpret_cast<float4*>(out + (size_t)bf * HW + p);
    __stcs(o,     r0);
    __stcs(o + 1, r1);
}

// ---------------------------------------------------------------------------
extern "C" void kernel_launch(void* const* d_in, const int* in_sizes, int n_in,
                              void* d_out, int out_size) {
    const float* nbr = (const float*)d_in[0];
    const float* ref = (const float*)d_in[1];
    float* out = (float*)d_out;

    ksum_kernel<<<BF * C, 256>>>(nbr);
    weight_kernel<<<BF * HW / 2048, 256>>>(ref, out);
}

// round 15
// speedup vs baseline: 1.0146x; 1.0146x over previous
#include <cuda_runtime.h>
#include <cuda_bf16.h>
#include <math.h>

// SpatialWeight — FINAL (best measured config; 82.4us observed).
// Problem: b=2, f=8, c=64, h=w=256  (fp32)
//   k_sum[bf,c] = sum_{hw} nbr[bf,c,hw]
//   out[bf,hw]  = sigmoid( sum_c ref[bf,c,hw] * k_sum[bf,c] )
// HBM streaming: 2 x 268MB reads + 4MB write.
// ksum ~39-41us @6.7-6.9TB/s; weight ~42.5-44us @6.2-6.4TB/s. Plateau
// verified across: load mechanism (LDG/cp.async/prefetch), request width
// (v4/v8), occupancy (27/55 warps), window size (4/8/16KB), channel order,
// store policy, L2 prefetch. 8KB windows + v8 + __ldcs/__stcs is optimal.

#define BF     16          // b*f
#define C      64
#define HW     65536       // 256*256
#define HW8    8192        // HW / 8

// 256-bit streaming load: 8 floats, 32B-aligned (Blackwell LDG.E.256).
__device__ __forceinline__ void ldcs_v8(const float* __restrict__ p,
                                        float& a, float& b, float& c, float& d,
                                        float& e, float& f, float& g, float& h) {
    asm volatile("ld.global.cs.v8.f32 {%0,%1,%2,%3,%4,%5,%6,%7}, [%8];"
                 : "=f"(a), "=f"(b), "=f"(c), "=f"(d),
                   "=f"(e), "=f"(f), "=f"(g), "=f"(h)
                 : "l"(p));
}

__device__ float g_ksum[BF * C];

// ---------------------------------------------------------------------------
// Kernel 1: per-channel-plane reduction. One block per (bf,c) plane (256 KB
// contiguous). 256 threads * 32 v8 streaming loads each.
// ---------------------------------------------------------------------------
__global__ __launch_bounds__(256) void ksum_kernel(const float* __restrict__ nbr) {
    const int ch = blockIdx.x;                       // 0..1023 == bf*64 + c
    const float* __restrict__ p = nbr + (size_t)ch * HW;

    float s = 0.0f;
    #pragma unroll 4
    for (int i = threadIdx.x; i < HW8; i += 256) {
        float a, b, c, d, e, f, g, h;
        ldcs_v8(p + (size_t)i * 8, a, b, c, d, e, f, g, h);
        s += ((a + b) + (c + d)) + ((e + f) + (g + h));
    }

    #pragma unroll
    for (int off = 16; off > 0; off >>= 1)
        s += __shfl_xor_sync(0xffffffffu, s, off);

    __shared__ float warp_sums[8];
    const int lane = threadIdx.x & 31;
    const int wid  = threadIdx.x >> 5;
    if (lane == 0) warp_sums[wid] = s;
    __syncthreads();

    if (wid == 0) {
        float t = (lane < 8) ? warp_sums[lane] : 0.0f;
        #pragma unroll
        for (int off = 4; off > 0; off >>= 1)
            t += __shfl_xor_sync(0xffffffffu, t, off);
        if (lane == 0) g_ksum[ch] = t;
    }
}

// ---------------------------------------------------------------------------
// Kernel 2: weighted channel contraction + sigmoid.
// 512 blocks x 256 threads, ONE v8 (32B) streaming load per thread per
// channel -> 8 KB contiguous window per channel step (measured optimum).
// __stcs streaming stores, fast-math sigmoid.
// ---------------------------------------------------------------------------
__global__ __launch_bounds__(256) void weight_kernel(const float* __restrict__ ref,
                                                     float* __restrict__ out) {
    const int bf  = blockIdx.x >> 5;                     // 32 blocks per bf
    const int win = (blockIdx.x & 31) << 11;             // window base (floats)
    const int p   = win + threadIdx.x * 8;               // float index in plane

    __shared__ float sk[C];
    if (threadIdx.x < C) sk[threadIdx.x] = g_ksum[bf * C + threadIdx.x];
    __syncthreads();

    const float* __restrict__ base = ref + (size_t)bf * C * HW + p;

    float a0 = 0.f, a1 = 0.f, a2 = 0.f, a3 = 0.f;
    float a4 = 0.f, a5 = 0.f, a6 = 0.f, a7 = 0.f;

    #pragma unroll
    for (int c = 0; c < C; c++) {
        float v0, v1, v2, v3, v4, v5, v6, v7;
        ldcs_v8(base + (size_t)c * HW, v0, v1, v2, v3, v4, v5, v6, v7);
        const float k = sk[c];
        a0 = fmaf(v0, k, a0);
        a1 = fmaf(v1, k, a1);
        a2 = fmaf(v2, k, a2);
        a3 = fmaf(v3, k, a3);
        a4 = fmaf(v4, k, a4);
        a5 = fmaf(v5, k, a5);
        a6 = fmaf(v6, k, a6);
        a7 = fmaf(v7, k, a7);
    }

    float4 r0, r1;
    r0.x = __fdividef(1.0f, 1.0f + __expf(-a0));
    r0.y = __fdividef(1.0f, 1.0f + __expf(-a1));
    r0.z = __fdividef(1.0f, 1.0f + __expf(-a2));
    r0.w = __fdividef(1.0f, 1.0f + __expf(-a3));
    r1.x = __fdividef(1.0f, 1.0f + __expf(-a4));
    r1.y = __fdividef(1.0f, 1.0f + __expf(-a5));
    r1.z = __fdividef(1.0f, 1.0f + __expf(-a6));
    r1.w = __fdividef(1.0f, 1.0f + __expf(-a7));

    float4* o = reinterpret_cast<float4*>(out + (size_t)bf * HW + p);
    __stcs(o,     r0);
    __stcs(o + 1, r1);
}

// ---------------------------------------------------------------------------
extern "C" void kernel_launch(void* const* d_in, const int* in_sizes, int n_in,
                              void* d_out, int out_size) {
    const float* nbr = (const float*)d_in[0];
    const float* ref = (const float*)d_in[1];
    float* out = (float*)d_out;

    ksum_kernel<<<BF * C, 256>>>(nbr);
    weight_kernel<<<BF * HW / 2048, 256>>>(ref, out);
}

// round 16
// speedup vs baseline: 1.0280x; 1.0132x over previous
#include <cuda_runtime.h>
#include <cuda_bf16.h>
#include <math.h>

// SpatialWeight — FINAL (best measured config; 82.4us best observed).
// Problem: b=2, f=8, c=64, h=w=256  (fp32)
//   k_sum[bf,c] = sum_{hw} nbr[bf,c,hw]
//   out[bf,hw]  = sigmoid( sum_c ref[bf,c,hw] * k_sum[bf,c] )
// HBM streaming: 2 x 268MB reads + 4MB write.
// ksum ~39-41us @6.7-6.9TB/s; weight ~42.5-44us @6.2-6.4TB/s. Plateau
// verified across: load mechanism (LDG/cp.async/L2-prefetch), request width
// (v4/v8), occupancy (27/55 warps), window size (4/8/16KB), channel order,
// store policy. 8KB windows + v8 streaming loads + __stcs is optimal.

#define BF     16          // b*f
#define C      64
#define HW     65536       // 256*256
#define HW8    8192        // HW / 8

// 256-bit streaming load: 8 floats, 32B-aligned (Blackwell LDG.E.256).
__device__ __forceinline__ void ldcs_v8(const float* __restrict__ p,
                                        float& a, float& b, float& c, float& d,
                                        float& e, float& f, float& g, float& h) {
    asm volatile("ld.global.cs.v8.f32 {%0,%1,%2,%3,%4,%5,%6,%7}, [%8];"
                 : "=f"(a), "=f"(b), "=f"(c), "=f"(d),
                   "=f"(e), "=f"(f), "=f"(g), "=f"(h)
                 : "l"(p));
}

__device__ float g_ksum[BF * C];

// ---------------------------------------------------------------------------
// Kernel 1: per-channel-plane reduction. One block per (bf,c) plane (256 KB
// contiguous). 256 threads * 32 v8 streaming loads each.
// ---------------------------------------------------------------------------
__global__ __launch_bounds__(256) void ksum_kernel(const float* __restrict__ nbr) {
    const int ch = blockIdx.x;                       // 0..1023 == bf*64 + c
    const float* __restrict__ p = nbr + (size_t)ch * HW;

    float s = 0.0f;
    #pragma unroll 4
    for (int i = threadIdx.x; i < HW8; i += 256) {
        float a, b, c, d, e, f, g, h;
        ldcs_v8(p + (size_t)i * 8, a, b, c, d, e, f, g, h);
        s += ((a + b) + (c + d)) + ((e + f) + (g + h));
    }

    #pragma unroll
    for (int off = 16; off > 0; off >>= 1)
        s += __shfl_xor_sync(0xffffffffu, s, off);

    __shared__ float warp_sums[8];
    const int lane = threadIdx.x & 31;
    const int wid  = threadIdx.x >> 5;
    if (lane == 0) warp_sums[wid] = s;
    __syncthreads();

    if (wid == 0) {
        float t = (lane < 8) ? warp_sums[lane] : 0.0f;
        #pragma unroll
        for (int off = 4; off > 0; off >>= 1)
            t += __shfl_xor_sync(0xffffffffu, t, off);
        if (lane == 0) g_ksum[ch] = t;
    }
}

// ---------------------------------------------------------------------------
// Kernel 2: weighted channel contraction + sigmoid.
// 512 blocks x 256 threads, ONE v8 (32B) streaming load per thread per
// channel -> 8 KB contiguous window per channel step (measured optimum).
// __stcs streaming stores, fast-math sigmoid.
// ---------------------------------------------------------------------------
__global__ __launch_bounds__(256) void weight_kernel(const float* __restrict__ ref,
                                                     float* __restrict__ out) {
    const int bf  = blockIdx.x >> 5;                     // 32 blocks per bf
    const int win = (blockIdx.x & 31) << 11;             // window base (floats)
    const int p   = win + threadIdx.x * 8;               // float index in plane

    __shared__ float sk[C];
    if (threadIdx.x < C) sk[threadIdx.x] = g_ksum[bf * C + threadIdx.x];
    __syncthreads();

    const float* __restrict__ base = ref + (size_t)bf * C * HW + p;

    float a0 = 0.f, a1 = 0.f, a2 = 0.f, a3 = 0.f;
    float a4 = 0.f, a5 = 0.f, a6 = 0.f, a7 = 0.f;

    #pragma unroll
    for (int c = 0; c < C; c++) {
        float v0, v1, v2, v3, v4, v5, v6, v7;
        ldcs_v8(base + (size_t)c * HW, v0, v1, v2, v3, v4, v5, v6, v7);
        const float k = sk[c];
        a0 = fmaf(v0, k, a0);
        a1 = fmaf(v1, k, a1);
        a2 = fmaf(v2, k, a2);
        a3 = fmaf(v3, k, a3);
        a4 = fmaf(v4, k, a4);
        a5 = fmaf(v5, k, a5);
        a6 = fmaf(v6, k, a6);
        a7 = fmaf(v7, k, a7);
    }

    float4 r0, r1;
    r0.x = __fdividef(1.0f, 1.0f + __expf(-a0));
    r0.y = __fdividef(1.0f, 1.0f + __expf(-a1));
    r0.z = __fdividef(1.0f, 1.0f + __expf(-a2));
    r0.w = __fdividef(1.0f, 1.0f + __expf(-a3));
    r1.x = __fdividef(1.0f, 1.0f + __expf(-a4));
    r1.y = __fdividef(1.0f, 1.0f + __expf(-a5));
    r1.z = __fdividef(1.0f, 1.0f + __expf(-a6));
    r1.w = __fdividef(1.0f, 1.0f + __expf(-a7));

    float4* o = reinterpret_cast<float4*>(out + (size_t)bf * HW + p);
    __stcs(o,     r0);
    __stcs(o + 1, r1);
}

// ---------------------------------------------------------------------------
extern "C" void kernel_launch(void* const* d_in, const int* in_sizes, int n_in,
                              void* d_out, int out_size) {
    const float* nbr = (const float*)d_in[0];
    const float* ref = (const float*)d_in[1];
    float* out = (float*)d_out;

    ksum_kernel<<<BF * C, 256>>>(nbr);
    weight_kernel<<<BF * HW / 2048, 256>>>(ref, out);
}

// round 17
// speedup vs baseline: 1.0475x; 1.0190x over previous
#include <cuda_runtime.h>
#include <cuda_bf16.h>
#include <math.h>

// SpatialWeight — fused single-kernel with per-bf software pipeline.
// Problem: b=2, f=8, c=64, h=w=256  (fp32)
//   k_sum[bf,c] = sum_{hw} nbr[bf,c,hw]
//   out[bf,hw]  = sigmoid( sum_c ref[bf,c,hw] * k_sum[bf,c] )
// Blocks 0..1023: ksum for plane (bf,c). Blocks 1024..1535: weight for an
// 8KB window; each waits only on ITS bf's 64-count flag -> K-tail overlaps
// W-head (mixed DRAM streams), removing the serial launch barrier.

#define BF       16
#define C        64
#define HW       65536
#define HW8      8192
#define NKBLK    1024          // ksum blocks (BF*C)
#define NWBLK    512           // weight blocks (32 per bf)

// 256-bit streaming load (Blackwell LDG.E.256).
__device__ __forceinline__ void ldcs_v8(const float* __restrict__ p,
                                        float& a, float& b, float& c, float& d,
                                        float& e, float& f, float& g, float& h) {
    asm volatile("ld.global.cs.v8.f32 {%0,%1,%2,%3,%4,%5,%6,%7}, [%8];"
                 : "=f"(a), "=f"(b), "=f"(c), "=f"(d),
                   "=f"(e), "=f"(f), "=f"(g), "=f"(h)
                 : "l"(p));
}

__device__ float g_ksum[BF * C];
__device__ int   g_done[BF];    // ksum blocks completed per bf (self-resets)
__device__ int   g_wdone[BF];   // weight blocks completed per bf (self-resets)

__global__ __launch_bounds__(256) void fused_kernel(const float* __restrict__ nbr,
                                                    const float* __restrict__ ref,
                                                    float* __restrict__ out) {
    const int bidx = blockIdx.x;
    const int tid  = threadIdx.x;

    if (bidx < NKBLK) {
        // ---------------- ksum phase: one (bf,c) plane, 256 KB contiguous ---
        const int ch = bidx;                        // bf = ch >> 6
        const float* __restrict__ p = nbr + (size_t)ch * HW;

        float s = 0.0f;
        #pragma unroll 4
        for (int i = tid; i < HW8; i += 256) {
            float a, b, c, d, e, f, g, h;
            ldcs_v8(p + (size_t)i * 8, a, b, c, d, e, f, g, h);
            s += ((a + b) + (c + d)) + ((e + f) + (g + h));
        }

        #pragma unroll
        for (int off = 16; off > 0; off >>= 1)
            s += __shfl_xor_sync(0xffffffffu, s, off);

        __shared__ float warp_sums[8];
        const int lane = tid & 31;
        const int wid  = tid >> 5;
        if (lane == 0) warp_sums[wid] = s;
        __syncthreads();

        if (wid == 0) {
            float t = (lane < 8) ? warp_sums[lane] : 0.0f;
            #pragma unroll
            for (int off = 4; off > 0; off >>= 1)
                t += __shfl_xor_sync(0xffffffffu, t, off);
            if (lane == 0) {
                g_ksum[ch] = t;
                __threadfence();                     // publish before flag
                atomicAdd(&g_done[ch >> 6], 1);
            }
        }
    } else {
        // ---------------- weight phase: one 8KB window, all 64 channels ----
        const int widx = bidx - NKBLK;
        const int bf   = widx >> 5;                  // 32 blocks per bf
        const int win  = (widx & 31) << 11;          // window base (floats)
        const int p    = win + tid * 8;

        // Wait until this bf's 64 channel sums are published.
        if (tid == 0) {
            while (atomicAdd(&g_done[bf], 0) < C)
                __nanosleep(128);
        }
        __syncthreads();
        __threadfence();                             // acquire g_ksum writes

        __shared__ float sk[C];
        if (tid < C) sk[tid] = g_ksum[bf * C + tid];
        __syncthreads();

        const float* __restrict__ base = ref + (size_t)bf * C * HW + p;

        float a0 = 0.f, a1 = 0.f, a2 = 0.f, a3 = 0.f;
        float a4 = 0.f, a5 = 0.f, a6 = 0.f, a7 = 0.f;

        #pragma unroll
        for (int c = 0; c < C; c++) {
            float v0, v1, v2, v3, v4, v5, v6, v7;
            ldcs_v8(base + (size_t)c * HW, v0, v1, v2, v3, v4, v5, v6, v7);
            const float k = sk[c];
            a0 = fmaf(v0, k, a0);
            a1 = fmaf(v1, k, a1);
            a2 = fmaf(v2, k, a2);
            a3 = fmaf(v3, k, a3);
            a4 = fmaf(v4, k, a4);
            a5 = fmaf(v5, k, a5);
            a6 = fmaf(v6, k, a6);
            a7 = fmaf(v7, k, a7);
        }

        float4 r0, r1;
        r0.x = __fdividef(1.0f, 1.0f + __expf(-a0));
        r0.y = __fdividef(1.0f, 1.0f + __expf(-a1));
        r0.z = __fdividef(1.0f, 1.0f + __expf(-a2));
        r0.w = __fdividef(1.0f, 1.0f + __expf(-a3));
        r1.x = __fdividef(1.0f, 1.0f + __expf(-a4));
        r1.y = __fdividef(1.0f, 1.0f + __expf(-a5));
        r1.z = __fdividef(1.0f, 1.0f + __expf(-a6));
        r1.w = __fdividef(1.0f, 1.0f + __expf(-a7));

        float4* o = reinterpret_cast<float4*>(out + (size_t)bf * HW + p);
        __stcs(o,     r0);
        __stcs(o + 1, r1);

        // Self-reset flags so every graph replay starts from zeroed state.
        __syncthreads();
        if (tid == 0) {
            int n = atomicAdd(&g_wdone[bf], 1);
            if (n == 31) {                           // last weight block of bf
                g_done[bf]  = 0;
                g_wdone[bf] = 0;
                __threadfence();
            }
        }
    }
}

// ---------------------------------------------------------------------------
extern "C" void kernel_launch(void* const* d_in, const int* in_sizes, int n_in,
                              void* d_out, int out_size) {
    const float* nbr = (const float*)d_in[0];
    const float* ref = (const float*)d_in[1];
    float* out = (float*)d_out;

    fused_kernel<<<NKBLK + NWBLK, 256>>>(nbr, ref, out);
}